// round 3
// baseline (speedup 1.0000x reference)
#include <cuda_runtime.h>
#include <cuda_bf16.h>
#include <math.h>

// out[i] = z[i] * dot(pos[i], c),  c = (w_tp/(2*sqrt(3))) * W1 @ W2 @ (W3 @ ones(3))
// W1: [3,2], W2: [2,2], W3: [2,3]  row-major.
// Single kernel; each thread processes 8 atoms (6 float4 pos loads, 2 int4 z, 2 float4 out).

__global__ void __launch_bounds__(256)
atoms_kernel(const float4* __restrict__ pos4,
             const int4*   __restrict__ z4,
             float4*       __restrict__ out4,
             const float*  __restrict__ w_tp,
             const float*  __restrict__ W1,
             const float*  __restrict__ W2,
             const float*  __restrict__ W3,
             int n8, int n) {
    // Fold MLP into 3-vector c (uniform across threads; loads broadcast + L1-cached)
    const float t30 = __ldg(&W3[0]) + __ldg(&W3[1]) + __ldg(&W3[2]);
    const float t31 = __ldg(&W3[3]) + __ldg(&W3[4]) + __ldg(&W3[5]);
    const float t20 = __ldg(&W2[0]) * t30 + __ldg(&W2[1]) * t31;
    const float t21 = __ldg(&W2[2]) * t30 + __ldg(&W2[3]) * t31;
    const float s   = __ldg(&w_tp[0]) * 0.28867513459481287f; // 1/(2*sqrt(3))
    const float c0  = (__ldg(&W1[0]) * t20 + __ldg(&W1[1]) * t21) * s;
    const float c1  = (__ldg(&W1[2]) * t20 + __ldg(&W1[3]) * t21) * s;
    const float c2  = (__ldg(&W1[4]) * t20 + __ldg(&W1[5]) * t21) * s;

    const int i = blockIdx.x * blockDim.x + threadIdx.x;
    if (i < n8) {
        const int pb = 6 * i;   // pos float4 base
        const int zb = 2 * i;   // z int4 base
        // issue all 8 loads up front for max MLP
        const float4 p0 = pos4[pb + 0];
        const float4 p1 = pos4[pb + 1];
        const float4 p2 = pos4[pb + 2];
        const float4 p3 = pos4[pb + 3];
        const float4 p4 = pos4[pb + 4];
        const float4 p5 = pos4[pb + 5];
        const int4   za = z4[zb + 0];
        const int4   zz = z4[zb + 1];

        float4 o0, o1;
        o0.x = (p0.x * c0 + p0.y * c1 + p0.z * c2) * (float)za.x;
        o0.y = (p0.w * c0 + p1.x * c1 + p1.y * c2) * (float)za.y;
        o0.z = (p1.z * c0 + p1.w * c1 + p2.x * c2) * (float)za.z;
        o0.w = (p2.y * c0 + p2.z * c1 + p2.w * c2) * (float)za.w;
        o1.x = (p3.x * c0 + p3.y * c1 + p3.z * c2) * (float)zz.x;
        o1.y = (p3.w * c0 + p4.x * c1 + p4.y * c2) * (float)zz.y;
        o1.z = (p4.z * c0 + p4.w * c1 + p5.x * c2) * (float)zz.z;
        o1.w = (p5.y * c0 + p5.z * c1 + p5.w * c2) * (float)zz.w;
        out4[zb + 0] = o0;
        out4[zb + 1] = o1;
    }

    // tail (n % 8 != 0) — dead for N=2M, kept for generality
    if ((n & 7) && blockIdx.x == 0 && threadIdx.x == 0) {
        const float* pos = (const float*)pos4;
        const int*   z   = (const int*)z4;
        float*       out = (float*)out4;
        for (int j = 8 * n8; j < n; j++) {
            out[j] = (pos[3 * j + 0] * c0 + pos[3 * j + 1] * c1 + pos[3 * j + 2] * c2)
                     * (float)z[j];
        }
    }
}

extern "C" void kernel_launch(void* const* d_in, const int* in_sizes, int n_in,
                              void* d_out, int out_size) {
    const float* pos  = (const float*)d_in[0];   // [N,3] f32
    const int*   z    = (const int*)d_in[1];     // [N]   i32
    const float* w_tp = (const float*)d_in[2];   // []    f32
    const float* W1   = (const float*)d_in[3];   // [3,2] f32
    const float* W2   = (const float*)d_in[4];   // [2,2] f32
    const float* W3   = (const float*)d_in[5];   // [2,3] f32
    float* out = (float*)d_out;

    const int n  = in_sizes[1];  // N atoms
    const int n8 = n >> 3;

    const int threads = 256;
    int blocks = (n8 + threads - 1) / threads;
    if (blocks < 1) blocks = 1;
    atoms_kernel<<<blocks, threads>>>((const float4*)pos, (const int4*)z,
                                      (float4*)out, w_tp, W1, W2, W3, n8, n);
}

// round 4
// speedup vs baseline: 1.2022x; 1.2022x over previous
#include <cuda_runtime.h>
#include <cuda_bf16.h>
#include <math.h>

// out[i] = z[i] * dot(pos[i], c),  c = (w_tp/(2*sqrt(3))) * W1 @ W2 @ (W3 @ ones(3))
// W1: [3,2], W2: [2,2], W3: [2,3]  row-major.
// Single kernel, 4 atoms/thread (3 float4 pos + 1 int4 z + 1 float4 out),
// weights folded in-kernel (uniform broadcast loads, overlapped with data latency).

__global__ void __launch_bounds__(256)
atoms_kernel(const float4* __restrict__ pos4,
             const int4*   __restrict__ z4,
             float4*       __restrict__ out4,
             const float*  __restrict__ w_tp,
             const float*  __restrict__ W1,
             const float*  __restrict__ W2,
             const float*  __restrict__ W3,
             int n4, int n) {
    const int i = blockIdx.x * blockDim.x + threadIdx.x;

    // Issue the wide data loads FIRST so they are in flight while the
    // uniform weight chain resolves. Streaming (evict-first) hints: read-once.
    float4 a, b, d; int4 zz;
    const bool valid = (i < n4);
    if (valid) {
        a  = __ldcs(&pos4[3 * i + 0]);
        b  = __ldcs(&pos4[3 * i + 1]);
        d  = __ldcs(&pos4[3 * i + 2]);
        zz = __ldcs(&z4[i]);
    }

    // Fold MLP into 3-vector c (uniform across warp; L1-hit broadcasts)
    const float t30 = __ldg(&W3[0]) + __ldg(&W3[1]) + __ldg(&W3[2]);
    const float t31 = __ldg(&W3[3]) + __ldg(&W3[4]) + __ldg(&W3[5]);
    const float t20 = __ldg(&W2[0]) * t30 + __ldg(&W2[1]) * t31;
    const float t21 = __ldg(&W2[2]) * t30 + __ldg(&W2[3]) * t31;
    const float s   = __ldg(&w_tp[0]) * 0.28867513459481287f; // 1/(2*sqrt(3))
    const float c0  = (__ldg(&W1[0]) * t20 + __ldg(&W1[1]) * t21) * s;
    const float c1  = (__ldg(&W1[2]) * t20 + __ldg(&W1[3]) * t21) * s;
    const float c2  = (__ldg(&W1[4]) * t20 + __ldg(&W1[5]) * t21) * s;

    if (valid) {
        float4 o;
        o.x = (a.x * c0 + a.y * c1 + a.z * c2) * (float)zz.x;
        o.y = (a.w * c0 + b.x * c1 + b.y * c2) * (float)zz.y;
        o.z = (b.z * c0 + b.w * c1 + d.x * c2) * (float)zz.z;
        o.w = (d.y * c0 + d.z * c1 + d.w * c2) * (float)zz.w;
        __stcs(&out4[i], o);   // streaming store, write-once
    }

    // tail (n % 4 != 0) — dead for N=2M, kept for generality
    if ((n & 3) && i == 0) {
        const float* pos = (const float*)pos4;
        const int*   z   = (const int*)z4;
        float*       out = (float*)out4;
        for (int j = 4 * n4; j < n; j++) {
            out[j] = (pos[3 * j + 0] * c0 + pos[3 * j + 1] * c1 + pos[3 * j + 2] * c2)
                     * (float)z[j];
        }
    }
}

extern "C" void kernel_launch(void* const* d_in, const int* in_sizes, int n_in,
                              void* d_out, int out_size) {
    const float* pos  = (const float*)d_in[0];   // [N,3] f32
    const int*   z    = (const int*)d_in[1];     // [N]   i32
    const float* w_tp = (const float*)d_in[2];   // []    f32
    const float* W1   = (const float*)d_in[3];   // [3,2] f32
    const float* W2   = (const float*)d_in[4];   // [2,2] f32
    const float* W3   = (const float*)d_in[5];   // [2,3] f32
    float* out = (float*)d_out;

    const int n  = in_sizes[1];  // N atoms
    const int n4 = n >> 2;

    const int threads = 256;
    int blocks = (n4 + threads - 1) / threads;
    if (blocks < 1) blocks = 1;
    atoms_kernel<<<blocks, threads>>>((const float4*)pos, (const int4*)z,
                                      (float4*)out, w_tp, W1, W2, W3, n4, n);
}